// round 1
// baseline (speedup 1.0000x reference)
#include <cuda_runtime.h>
#include <math.h>

#define SEQ 2048
#define BATCH 16
#define HID 1024

// Scratch (allocation-free rule: __device__ globals)
__device__ float g_energy[BATCH * HID];   // [B, H]
__device__ float g_scores[SEQ * BATCH];   // [S, B]

// ---------------------------------------------------------------------------
// Kernel 1: energy[b][j] = sum_h state[b][h] * W[j][h] + bias[j]
// One warp per j. Lanes stride h (coalesced W row reads). 16 accumulators.
// ---------------------------------------------------------------------------
__global__ void __launch_bounds__(256) energy_kernel(
    const float* __restrict__ state,   // [B, H] (= last_decoder_state[0,0])
    const float* __restrict__ W,       // [H, H]
    const float* __restrict__ bias)    // [H]
{
    int gwarp = (blockIdx.x * blockDim.x + threadIdx.x) >> 5;
    int lane  = threadIdx.x & 31;
    if (gwarp >= HID) return;
    const int j = gwarp;

    float acc[BATCH];
#pragma unroll
    for (int b = 0; b < BATCH; b++) acc[b] = 0.0f;

    const float* wrow = W + (size_t)j * HID;
#pragma unroll 4
    for (int k = 0; k < HID / 32; k++) {
        int h = lane + k * 32;
        float wv = wrow[h];
#pragma unroll
        for (int b = 0; b < BATCH; b++)
            acc[b] = fmaf(wv, state[b * HID + h], acc[b]);
    }

#pragma unroll
    for (int b = 0; b < BATCH; b++) {
#pragma unroll
        for (int off = 16; off > 0; off >>= 1)
            acc[b] += __shfl_xor_sync(0xffffffffu, acc[b], off);
    }
    // After xor-reduce every lane has the sum; lanes 0..15 write their b.
    if (lane < BATCH)
        g_energy[lane * HID + j] = acc[lane] + bias[j];
}

// ---------------------------------------------------------------------------
// Kernel 2: scores[s][b] = dot(enc[s][b][:], energy[b][:])  (H = 1024)
// One block per s, 16 warps = 16 b's. float4 loads, 8 iters/lane (MLP=8).
// This kernel streams the full 134 MB of encoder_output -> HBM-bound.
// ---------------------------------------------------------------------------
__global__ void __launch_bounds__(512) scores_kernel(
    const float* __restrict__ enc)     // [S, B, H]
{
    int s    = blockIdx.x;
    int b    = threadIdx.x >> 5;
    int lane = threadIdx.x & 31;

    const float4* e  = (const float4*)(enc + ((size_t)s * BATCH + b) * HID);
    const float4* en = (const float4*)(g_energy + b * HID);

    float acc = 0.0f;
#pragma unroll
    for (int i = 0; i < HID / 4 / 32; i++) {       // 8 iterations
        float4 a = e[lane + i * 32];
        float4 c = en[lane + i * 32];
        acc = fmaf(a.x, c.x, acc);
        acc = fmaf(a.y, c.y, acc);
        acc = fmaf(a.z, c.z, acc);
        acc = fmaf(a.w, c.w, acc);
    }
#pragma unroll
    for (int off = 16; off > 0; off >>= 1)
        acc += __shfl_xor_sync(0xffffffffu, acc, off);
    if (lane == 0)
        g_scores[s * BATCH + b] = acc;
}

// ---------------------------------------------------------------------------
// Kernel 3: softmax over S (axis 0) for each b; output layout [1,1,S,B].
// One block per b.
// ---------------------------------------------------------------------------
__global__ void __launch_bounds__(256) softmax_kernel(float* __restrict__ out)
{
    const int b   = blockIdx.x;
    const int tid = threadIdx.x;
    __shared__ float red[32];
    const int nw = 256 / 32;
    int warp = tid >> 5, lane = tid & 31;

    // pass 1: max
    float m = -INFINITY;
    for (int s = tid; s < SEQ; s += 256)
        m = fmaxf(m, g_scores[s * BATCH + b]);
#pragma unroll
    for (int off = 16; off > 0; off >>= 1)
        m = fmaxf(m, __shfl_xor_sync(0xffffffffu, m, off));
    if (lane == 0) red[warp] = m;
    __syncthreads();
    if (warp == 0) {
        float v = (lane < nw) ? red[lane] : -INFINITY;
#pragma unroll
        for (int off = 16; off > 0; off >>= 1)
            v = fmaxf(v, __shfl_xor_sync(0xffffffffu, v, off));
        if (lane == 0) red[0] = v;
    }
    __syncthreads();
    m = red[0];
    __syncthreads();

    // pass 2: sum of exp
    float sum = 0.0f;
    for (int s = tid; s < SEQ; s += 256)
        sum += __expf(g_scores[s * BATCH + b] - m);
#pragma unroll
    for (int off = 16; off > 0; off >>= 1)
        sum += __shfl_xor_sync(0xffffffffu, sum, off);
    if (lane == 0) red[warp] = sum;
    __syncthreads();
    if (warp == 0) {
        float v = (lane < nw) ? red[lane] : 0.0f;
#pragma unroll
        for (int off = 16; off > 0; off >>= 1)
            v += __shfl_xor_sync(0xffffffffu, v, off);
        if (lane == 0) red[0] = v;
    }
    __syncthreads();
    const float inv = 1.0f / red[0];

    // pass 3: write
    for (int s = tid; s < SEQ; s += 256)
        out[s * BATCH + b] = __expf(g_scores[s * BATCH + b] - m) * inv;
}

// ---------------------------------------------------------------------------
extern "C" void kernel_launch(void* const* d_in, const int* in_sizes, int n_in,
                              void* d_out, int out_size)
{
    const float* enc   = (const float*)d_in[0];   // [S, B, H]
    const float* lds   = (const float*)d_in[1];   // [2, 1, B, H]
    const float* W     = (const float*)d_in[2];   // [H, H]
    const float* bias  = (const float*)d_in[3];   // [H]
    float* out = (float*)d_out;                   // [1, 1, S, B]

    // state = last_decoder_state[0, 0] -> first B*H floats
    energy_kernel<<<HID * 32 / 256, 256>>>(lds, W, bias);
    scores_kernel<<<SEQ, 512>>>(enc);
    softmax_kernel<<<BATCH, 256>>>(out);
}

// round 2
// speedup vs baseline: 2.4388x; 2.4388x over previous
#include <cuda_runtime.h>
#include <math.h>

#define SEQ 2048
#define BATCH 16
#define HID 1024

// Scratch (allocation-free rule: __device__ globals)
__device__ float g_energy[BATCH * HID];   // [B, H]
__device__ float g_scores[SEQ * BATCH];   // [S, B]

// ---------------------------------------------------------------------------
// Kernel 1: energy[b][j] = sum_h state[b][h] * W[j][h] + bias[j]
// Register-tiled micro-GEMM:
//   - state (64KB) cached in shared memory per block
//   - grid: 128 blocks x 8 warps; block owns 8 j's
//   - warp(w): jgroup = w&1 (4 j's), bgroup = w>>2... see mapping below
//     warp computes a 4j x 4b tile over the FULL H (no cross-warp reduce)
//   - all loads float4; W rows L1-hot (reused by 4 warps in-block)
// ---------------------------------------------------------------------------
__global__ void __launch_bounds__(256) energy_kernel(
    const float* __restrict__ state,   // [B, H] (= last_decoder_state[0,0])
    const float* __restrict__ W,       // [H, H]
    const float* __restrict__ bias)    // [H]
{
    __shared__ float s_state[BATCH * HID];   // 64KB

    const int tid  = threadIdx.x;
    const int warp = tid >> 5;
    const int lane = tid & 31;

    // cooperative load of state into smem (float4, coalesced)
    {
        const float4* src = (const float4*)state;
        float4* dst = (float4*)s_state;
#pragma unroll
        for (int i = 0; i < (BATCH * HID / 4) / 256; i++)   // 16 iters
            dst[tid + i * 256] = src[tid + i * 256];
    }
    __syncthreads();

    // warp tile: jgroup in {0,1} -> 4 j's, bgroup in {0..3} -> 4 b's
    const int jgroup = warp & 1;
    const int bgroup = warp >> 1;
    const int j0 = blockIdx.x * 8 + jgroup * 4;
    const int b0 = bgroup * 4;

    const float4* w0 = (const float4*)(W + (size_t)(j0 + 0) * HID);
    const float4* w1 = (const float4*)(W + (size_t)(j0 + 1) * HID);
    const float4* w2 = (const float4*)(W + (size_t)(j0 + 2) * HID);
    const float4* w3 = (const float4*)(W + (size_t)(j0 + 3) * HID);
    const float4* s0 = (const float4*)(s_state + (b0 + 0) * HID);
    const float4* s1 = (const float4*)(s_state + (b0 + 1) * HID);
    const float4* s2 = (const float4*)(s_state + (b0 + 2) * HID);
    const float4* s3 = (const float4*)(s_state + (b0 + 3) * HID);

    float acc[4][4];
#pragma unroll
    for (int a = 0; a < 4; a++)
#pragma unroll
        for (int c = 0; c < 4; c++) acc[a][c] = 0.0f;

#pragma unroll
    for (int k = 0; k < (HID / 4) / 32; k++) {   // 8 iterations
        const int idx = lane + k * 32;
        float4 wv[4], sv[4];
        wv[0] = w0[idx]; wv[1] = w1[idx]; wv[2] = w2[idx]; wv[3] = w3[idx];
        sv[0] = s0[idx]; sv[1] = s1[idx]; sv[2] = s2[idx]; sv[3] = s3[idx];
#pragma unroll
        for (int jj = 0; jj < 4; jj++) {
#pragma unroll
            for (int bb = 0; bb < 4; bb++) {
                acc[jj][bb] = fmaf(wv[jj].x, sv[bb].x, acc[jj][bb]);
                acc[jj][bb] = fmaf(wv[jj].y, sv[bb].y, acc[jj][bb]);
                acc[jj][bb] = fmaf(wv[jj].z, sv[bb].z, acc[jj][bb]);
                acc[jj][bb] = fmaf(wv[jj].w, sv[bb].w, acc[jj][bb]);
            }
        }
    }

    // warp-level xor reduce: every lane ends with the full sums
#pragma unroll
    for (int jj = 0; jj < 4; jj++)
#pragma unroll
        for (int bb = 0; bb < 4; bb++)
#pragma unroll
            for (int off = 16; off > 0; off >>= 1)
                acc[jj][bb] += __shfl_xor_sync(0xffffffffu, acc[jj][bb], off);

    // lanes 0..15 write: lane = bb*4 + jj
    if (lane < 16) {
        const int bb = lane >> 2;
        const int jj = lane & 3;
        g_energy[(b0 + bb) * HID + (j0 + jj)] = acc[jj][bb] + bias[j0 + jj];
    }
}

// ---------------------------------------------------------------------------
// Kernel 2: scores[s][b] = dot(enc[s][b][:], energy[b][:])  (H = 1024)
// One block per s, 16 warps = 16 b's. float4 loads, 8 iters/lane (MLP=8).
// Streams the full 134 MB of encoder_output -> HBM-bound (~21us floor).
// ---------------------------------------------------------------------------
__global__ void __launch_bounds__(512) scores_kernel(
    const float* __restrict__ enc)     // [S, B, H]
{
    int s    = blockIdx.x;
    int b    = threadIdx.x >> 5;
    int lane = threadIdx.x & 31;

    const float4* e  = (const float4*)(enc + ((size_t)s * BATCH + b) * HID);
    const float4* en = (const float4*)(g_energy + b * HID);

    float acc = 0.0f;
#pragma unroll
    for (int i = 0; i < HID / 4 / 32; i++) {       // 8 iterations
        float4 a = e[lane + i * 32];
        float4 c = en[lane + i * 32];
        acc = fmaf(a.x, c.x, acc);
        acc = fmaf(a.y, c.y, acc);
        acc = fmaf(a.z, c.z, acc);
        acc = fmaf(a.w, c.w, acc);
    }
#pragma unroll
    for (int off = 16; off > 0; off >>= 1)
        acc += __shfl_xor_sync(0xffffffffu, acc, off);
    if (lane == 0)
        g_scores[s * BATCH + b] = acc;
}

// ---------------------------------------------------------------------------
// Kernel 3: softmax over S (axis 0) for each b; output layout [1,1,S,B].
// One block per b; scores are L2-hot (128KB).
// ---------------------------------------------------------------------------
__global__ void __launch_bounds__(256) softmax_kernel(float* __restrict__ out)
{
    const int b   = blockIdx.x;
    const int tid = threadIdx.x;
    __shared__ float red[32];
    const int nw = 256 / 32;
    int warp = tid >> 5, lane = tid & 31;

    // pass 1: max
    float m = -INFINITY;
#pragma unroll
    for (int i = 0; i < SEQ / 256; i++)
        m = fmaxf(m, g_scores[(tid + i * 256) * BATCH + b]);
#pragma unroll
    for (int off = 16; off > 0; off >>= 1)
        m = fmaxf(m, __shfl_xor_sync(0xffffffffu, m, off));
    if (lane == 0) red[warp] = m;
    __syncthreads();
    if (warp == 0) {
        float v = (lane < nw) ? red[lane] : -INFINITY;
#pragma unroll
        for (int off = 16; off > 0; off >>= 1)
            v = fmaxf(v, __shfl_xor_sync(0xffffffffu, v, off));
        if (lane == 0) red[0] = v;
    }
    __syncthreads();
    m = red[0];
    __syncthreads();

    // pass 2: sum of exp
    float sum = 0.0f;
#pragma unroll
    for (int i = 0; i < SEQ / 256; i++)
        sum += __expf(g_scores[(tid + i * 256) * BATCH + b] - m);
#pragma unroll
    for (int off = 16; off > 0; off >>= 1)
        sum += __shfl_xor_sync(0xffffffffu, sum, off);
    if (lane == 0) red[warp] = sum;
    __syncthreads();
    if (warp == 0) {
        float v = (lane < nw) ? red[lane] : 0.0f;
#pragma unroll
        for (int off = 16; off > 0; off >>= 1)
            v += __shfl_xor_sync(0xffffffffu, v, off);
        if (lane == 0) red[0] = v;
    }
    __syncthreads();
    const float inv = 1.0f / red[0];

    // pass 3: write
#pragma unroll
    for (int i = 0; i < SEQ / 256; i++) {
        int s = tid + i * 256;
        out[s * BATCH + b] = __expf(g_scores[s * BATCH + b] - m) * inv;
    }
}

// ---------------------------------------------------------------------------
extern "C" void kernel_launch(void* const* d_in, const int* in_sizes, int n_in,
                              void* d_out, int out_size)
{
    const float* enc   = (const float*)d_in[0];   // [S, B, H]
    const float* lds   = (const float*)d_in[1];   // [2, 1, B, H]
    const float* W     = (const float*)d_in[2];   // [H, H]
    const float* bias  = (const float*)d_in[3];   // [H]
    float* out = (float*)d_out;                   // [1, 1, S, B]

    // state = last_decoder_state[0, 0] -> first B*H floats
    energy_kernel<<<HID / 8, 256>>>(lds, W, bias);
    scores_kernel<<<SEQ, 512>>>(enc);
    softmax_kernel<<<BATCH, 256>>>(out);
}